// round 2
// baseline (speedup 1.0000x reference)
#include <cuda_runtime.h>
#include <cuda_bf16.h>
#include <stdint.h>

#define BATCH 16384
#define NIN   128
#define NFEAT 8384
#define NOUT  512

#define BM 128
#define BN 128
#define BK 32
#define NCHUNK (NFEAT / BK)   // 262
#define THREADS 256

// ---- global scratch (static __device__, no allocs) ----
__device__ __align__(16) __nv_bfloat16 g_Wt_hi[(size_t)NOUT * NFEAT];  // [n][k] bf16 hi
__device__ __align__(16) __nv_bfloat16 g_Wt_lo[(size_t)NOUT * NFEAT];  // [n][k] bf16 lo
__device__ __align__(16) unsigned short g_tab[NFEAT];                  // i | (j<<8); j=128 => linear

// ===================== prep kernels =====================

__global__ void k_tab() {
    int f = blockIdx.x * 256 + threadIdx.x;
    if (f >= NFEAT) return;
    int i, j;
    if (f < NIN) { i = f; j = NIN; }  // linear term: x[i] * xs[..][128]==1.0
    else {
        int t = f - NIN;
        i = 0;
        while (NIN * (i + 1) - (i + 1) * i / 2 <= t) i++;
        j = i + (t - (NIN * i - i * (i - 1) / 2));
    }
    g_tab[f] = (unsigned short)(i | (j << 8));
}

// transpose W [8384,512] f32 -> Wt_hi/Wt_lo [512,8384] bf16 (split)
__global__ void k_wt(const float* __restrict__ W) {
    __shared__ float sm[64][65];
    int k0 = blockIdx.x * 64, n0 = blockIdx.y * 64;
    int tid = threadIdx.x;
    for (int idx = tid; idx < 64 * 64; idx += 256) {
        int r = idx >> 6, c = idx & 63;           // r: k-local, c: n-local
        sm[c][r] = W[(size_t)(k0 + r) * NOUT + n0 + c];
    }
    __syncthreads();
    for (int idx = tid; idx < 64 * 32; idx += 256) {
        int nl = idx >> 5, kl = (idx & 31) * 2;
        float v0 = sm[nl][kl], v1 = sm[nl][kl + 1];
        __nv_bfloat16 h0 = __float2bfloat16(v0), h1 = __float2bfloat16(v1);
        float l0 = v0 - __bfloat162float(h0);
        float l1 = v1 - __bfloat162float(h1);
        __nv_bfloat16 e0 = __float2bfloat16(l0), e1 = __float2bfloat16(l1);
        unsigned int hp = (unsigned int)__bfloat16_as_ushort(h0) |
                          ((unsigned int)__bfloat16_as_ushort(h1) << 16);
        unsigned int lp = (unsigned int)__bfloat16_as_ushort(e0) |
                          ((unsigned int)__bfloat16_as_ushort(e1) << 16);
        size_t o = (size_t)(n0 + nl) * NFEAT + k0 + kl;   // even
        *(unsigned int*)((unsigned short*)g_Wt_hi + o) = hp;
        *(unsigned int*)((unsigned short*)g_Wt_lo + o) = lp;
    }
}

// ===================== PTX helpers (sm_80-compatible) =====================

__device__ __forceinline__ uint32_t smem_u32(const void* p) {
    uint32_t a;
    asm("{ .reg .u64 t; cvta.to.shared.u64 t, %1; cvt.u32.u64 %0, t; }" : "=r"(a) : "l"(p));
    return a;
}

__device__ __forceinline__ void ldsm4(uint32_t* r, uint32_t addr) {
    asm volatile("ldmatrix.sync.aligned.m8n8.x4.shared.b16 {%0,%1,%2,%3}, [%4];"
                 : "=r"(r[0]), "=r"(r[1]), "=r"(r[2]), "=r"(r[3]) : "r"(addr));
}

__device__ __forceinline__ void mma_bf16(float* d, const uint32_t* a, const uint32_t* b) {
    asm volatile(
        "mma.sync.aligned.m16n8k16.row.col.f32.bf16.bf16.f32 "
        "{%0,%1,%2,%3}, {%4,%5,%6,%7}, {%8,%9}, {%0,%1,%2,%3};"
        : "+f"(d[0]), "+f"(d[1]), "+f"(d[2]), "+f"(d[3])
        : "r"(a[0]), "r"(a[1]), "r"(a[2]), "r"(a[3]), "r"(b[0]), "r"(b[1]));
}

// ===================== main kernel =====================
// SMEM layout:
//   buffer p (p=0,1) at p*40960:
//     Ah 128x40bf16 (80B row stride) = 10240 | Al +10240 | Bh +20480 | Bl +30720
//   xs (fp32, 128 x 129, xs[m][128]=1.0) at 81920 (66048 B)
#define ROWB  80                      // bytes per SMEM row (40 bf16, conflict-free ldmatrix)
#define SM_AH(p) ((p) * 40960 + 0)
#define SM_AL(p) ((p) * 40960 + 10240)
#define SM_BH(p) ((p) * 40960 + 20480)
#define SM_BL(p) ((p) * 40960 + 30720)
#define SM_XS    81920
#define SMEM_BYTES (SM_XS + 128 * 129 * 4)

__global__ void __launch_bounds__(THREADS, 1)
k_main(const float* __restrict__ X, const float* __restrict__ bias,
       float* __restrict__ out) {
    extern __shared__ char sm[];
    const int tid = threadIdx.x;
    const int lane = tid & 31;
    const int wid = tid >> 5;
    const int warp_m = wid & 3;       // 4 warps along M
    const int warp_n = wid >> 2;      // 2 warps along N
    const int n0 = blockIdx.x * BN;
    const int m0 = blockIdx.y * BM;

    float* xs = (float*)(sm + SM_XS);

    // ---- load x tile (fp32), pad col 128 with 1.0 ----
    for (int idx = tid; idx < BM * NIN; idx += THREADS) {
        int m = idx >> 7, k = idx & 127;
        xs[m * 129 + k] = X[(size_t)(m0 + m) * NIN + k];
    }
    if (tid < BM) xs[tid * 129 + 128] = 1.0f;

    // per-thread production constants
    const int ml = tid & 127;         // row (A: m-row, B: n-row)
    const int kh = tid >> 7;          // which 16-feature half of the 32-chunk
    const float* xrow = &xs[ml * 129];
    const __nv_bfloat16* wth = g_Wt_hi + (size_t)(n0 + ml) * NFEAT + kh * 16;
    const __nv_bfloat16* wtl = g_Wt_lo + (size_t)(n0 + ml) * NFEAT + kh * 16;

    float acc[2][8][4];
    #pragma unroll
    for (int a = 0; a < 2; ++a)
        #pragma unroll
        for (int b = 0; b < 8; ++b)
            #pragma unroll
            for (int c = 0; c < 4; ++c) acc[a][b][c] = 0.0f;

    // precomputed ldmatrix smem offsets (within a buffer)
    const uint32_t sbase = smem_u32(sm);
    // A x4: rows warp_m*32 + mt*16 + (lane&15), k-half (lane>>4)
    const uint32_t a_row = (uint32_t)(warp_m * 32 + (lane & 15));
    const uint32_t a_off = a_row * ROWB + (uint32_t)((lane >> 4) * 16);
    // B x4 (two n8 frags): rows warp_n*64 + np*16 + (lane>>4)*8 + (lane&7), k-half (lane>>3)&1
    const uint32_t b_row = (uint32_t)(warp_n * 64 + ((lane >> 4) << 3) + (lane & 7));
    const uint32_t b_off = b_row * ROWB + (uint32_t)(((lane >> 3) & 1) * 16);

    auto produce = [&](int p, int c) {
        char* Ah = sm + SM_AH(p);
        char* Al = sm + SM_AL(p);
        char* Bh = sm + SM_BH(p);
        char* Bl = sm + SM_BL(p);
        const int f0 = c * BK + kh * 16;
        const uint4* tabv = (const uint4*)&g_tab[f0];   // 8 pairs per uint4
        #pragma unroll
        for (int g = 0; g < 2; ++g) {
            uint4 tv = __ldg(tabv + g);
            uint32_t tw[4] = {tv.x, tv.y, tv.z, tv.w};
            uint4 HP, LP;
            uint32_t* hp = (uint32_t*)&HP;
            uint32_t* lp = (uint32_t*)&LP;
            #pragma unroll
            for (int q = 0; q < 4; ++q) {
                uint32_t wv = tw[q];
                int i0 = wv & 255, j0 = (wv >> 8) & 255;
                int i1 = (wv >> 16) & 255, j1 = (wv >> 24) & 255;
                float v0 = xrow[i0] * xrow[j0];
                float v1 = xrow[i1] * xrow[j1];
                uint32_t h;
                asm("cvt.rn.bf16x2.f32 %0, %1, %2;" : "=r"(h) : "f"(v1), "f"(v0));
                __nv_bfloat162 h2 = *(__nv_bfloat162*)&h;
                float2 hf = __bfloat1622float2(h2);
                float l0 = v0 - hf.x, l1 = v1 - hf.y;
                uint32_t l;
                asm("cvt.rn.bf16x2.f32 %0, %1, %2;" : "=r"(l) : "f"(l1), "f"(l0));
                hp[q] = h; lp[q] = l;
            }
            uint32_t off = (uint32_t)(ml * ROWB + (kh * 16 + g * 8) * 2);
            *(uint4*)(Ah + off) = HP;
            *(uint4*)(Al + off) = LP;
        }
        // stage B: 16 bf16 hi + lo for n-row ml
        {
            const uint4* wh4 = (const uint4*)(wth + (size_t)c * BK);
            const uint4* wl4 = (const uint4*)(wtl + (size_t)c * BK);
            uint4 w0 = __ldg(wh4), w1 = __ldg(wh4 + 1);
            uint4 y0 = __ldg(wl4), y1 = __ldg(wl4 + 1);
            uint32_t off = (uint32_t)(ml * ROWB + kh * 32);
            *(uint4*)(Bh + off) = w0; *(uint4*)(Bh + off + 16) = w1;
            *(uint4*)(Bl + off) = y0; *(uint4*)(Bl + off + 16) = y1;
        }
    };

    auto compute = [&](int p) {
        const uint32_t base = sbase + (uint32_t)(p * 40960);
        #pragma unroll
        for (int ks = 0; ks < 2; ++ks) {
            uint32_t Afh[2][4], Afl[2][4], Bfh[4][4], Bfl[4][4];
            const uint32_t kso = (uint32_t)(ks * 32);
            #pragma unroll
            for (int mt = 0; mt < 2; ++mt) {
                uint32_t ao = a_off + (uint32_t)(mt * 16 * ROWB) + kso;
                ldsm4(Afh[mt], base + 0     + ao);
                ldsm4(Afl[mt], base + 10240 + ao);
            }
            #pragma unroll
            for (int np = 0; np < 4; ++np) {
                uint32_t bo = b_off + (uint32_t)(np * 16 * ROWB) + kso;
                ldsm4(Bfh[np], base + 20480 + bo);
                ldsm4(Bfl[np], base + 30720 + bo);
            }
            #pragma unroll
            for (int mt = 0; mt < 2; ++mt)
                #pragma unroll
                for (int np = 0; np < 4; ++np)
                    #pragma unroll
                    for (int h2 = 0; h2 < 2; ++h2) {
                        int nt = np * 2 + h2;
                        mma_bf16(acc[mt][nt], Afh[mt], &Bfh[np][h2 * 2]);
                        mma_bf16(acc[mt][nt], Afh[mt], &Bfl[np][h2 * 2]);
                        mma_bf16(acc[mt][nt], Afl[mt], &Bfh[np][h2 * 2]);
                    }
        }
    };

    // ---- pipelined mainloop (double buffer, 1 sync/chunk) ----
    __syncthreads();          // xs ready
    produce(0, 0);
    #pragma unroll 1
    for (int c = 0; c < NCHUNK; ++c) {
        __syncthreads();
        if (c + 1 < NCHUNK) produce((c + 1) & 1, c + 1);
        compute(c & 1);
    }

    // ---- epilogue ----
    const int gid = lane >> 2, tig = lane & 3;
    #pragma unroll
    for (int mt = 0; mt < 2; ++mt) {
        #pragma unroll
        for (int nt = 0; nt < 8; ++nt) {
            int row = m0 + warp_m * 32 + mt * 16 + gid;
            int col = n0 + warp_n * 64 + nt * 8 + tig * 2;
            float b0 = bias[col], b1 = bias[col + 1];
            float2 v0 = {acc[mt][nt][0] + b0, acc[mt][nt][1] + b1};
            float2 v1 = {acc[mt][nt][2] + b0, acc[mt][nt][3] + b1};
            *(float2*)(out + (size_t)row * NOUT + col) = v0;
            *(float2*)(out + (size_t)(row + 8) * NOUT + col) = v1;
        }
    }
}

// ===================== launcher =====================

extern "C" void kernel_launch(void* const* d_in, const int* in_sizes, int n_in,
                              void* d_out, int out_size) {
    const float* x = (const float*)d_in[0];
    const float* w = (const float*)d_in[1];
    const float* b = (const float*)d_in[2];
    float* out = (float*)d_out;

    static int attr_set = 0;
    cudaFuncSetAttribute(k_main, cudaFuncAttributeMaxDynamicSharedMemorySize, SMEM_BYTES);
    (void)attr_set;

    k_tab<<<(NFEAT + 255) / 256, 256>>>();
    k_wt<<<dim3(NFEAT / 64, NOUT / 64), 256>>>(w);
    k_main<<<dim3(NOUT / BN, BATCH / BM), THREADS, SMEM_BYTES>>>(x, b, out);
}

// round 3
// speedup vs baseline: 2.4735x; 2.4735x over previous
#include <cuda_runtime.h>
#include <cuda_fp16.h>
#include <stdint.h>

#define BATCH 16384
#define NIN   128
#define NFEAT 8384
#define NOUT  512

#define BM 128
#define BN 128
#define BK 64
#define NCHUNK (NFEAT / BK)   // 131
#define THREADS 256
#define NSTAGE 3

// ---- global scratch (static __device__, no allocs) ----
__device__ __align__(16) __half g_Ah[(size_t)BATCH * NFEAT];   // expanded features hi (274.7MB)
__device__ __align__(16) __half g_Al[(size_t)BATCH * NFEAT];   // expanded features lo
__device__ __align__(16) __half g_Wt[(size_t)NOUT * NFEAT];    // W^T fp16 [n][k]
__device__ __align__(16) unsigned short g_tab[NFEAT];          // i | (j<<8); j=128 => linear

// ===================== prep kernels =====================

__global__ void k_tab() {
    int f = blockIdx.x * 256 + threadIdx.x;
    if (f >= NFEAT) return;
    int i, j;
    if (f < NIN) { i = f; j = NIN; }  // linear term: x[i] * 1.0
    else {
        int t = f - NIN;
        i = 0;
        while (NIN * (i + 1) - (i + 1) * i / 2 <= t) i++;
        j = i + (t - (NIN * i - i * (i - 1) / 2));
    }
    g_tab[f] = (unsigned short)(i | (j << 8));
}

// transpose W [8384,512] f32 -> Wt [512,8384] fp16
__global__ void k_wt(const float* __restrict__ W) {
    __shared__ float sm[64][65];
    int k0 = blockIdx.x * 64, n0 = blockIdx.y * 64;
    int tid = threadIdx.x;
    for (int idx = tid; idx < 64 * 64; idx += 256) {
        int r = idx >> 6, c = idx & 63;           // r: k-local, c: n-local
        sm[c][r] = W[(size_t)(k0 + r) * NOUT + n0 + c];
    }
    __syncthreads();
    for (int idx = tid; idx < 64 * 32; idx += 256) {
        int nl = idx >> 5, kl = (idx & 31) * 2;
        float v0 = sm[nl][kl], v1 = sm[nl][kl + 1];
        uint32_t h;
        asm("cvt.rn.f16x2.f32 %0, %1, %2;" : "=r"(h) : "f"(v1), "f"(v0));
        size_t o = (size_t)(n0 + nl) * NFEAT + k0 + kl;   // even
        *(uint32_t*)((unsigned short*)g_Wt + o) = h;
    }
}

// expand X -> fp16 hi/lo feature matrix [BATCH][NFEAT]
__global__ void __launch_bounds__(256, 4) k_expand(const float* __restrict__ X) {
    __shared__ float xs[129];
    const int b = blockIdx.x;
    const int tid = threadIdx.x;
    if (tid < 128) xs[tid] = X[(size_t)b * NIN + tid];
    if (tid == 0) xs[128] = 1.0f;
    __syncthreads();

    __half* Ah = g_Ah + (size_t)b * NFEAT;
    __half* Al = g_Al + (size_t)b * NFEAT;
    #pragma unroll 1
    for (int g = tid; g < NFEAT / 8; g += 256) {       // 1048 groups of 8 feats
        uint4 tv = *(const uint4*)&g_tab[g * 8];
        uint32_t tw[4] = {tv.x, tv.y, tv.z, tv.w};
        uint4 HP, LP;
        uint32_t* hp = (uint32_t*)&HP;
        uint32_t* lp = (uint32_t*)&LP;
        #pragma unroll
        for (int q = 0; q < 4; ++q) {
            uint32_t wv = tw[q];
            int i0 = wv & 255, j0 = (wv >> 8) & 255;
            int i1 = (wv >> 16) & 255, j1 = (wv >> 24) & 255;
            float v0 = xs[i0] * xs[j0];
            float v1 = xs[i1] * xs[j1];
            uint32_t h;
            asm("cvt.rn.f16x2.f32 %0, %1, %2;" : "=r"(h) : "f"(v1), "f"(v0));
            float2 hf = __half22float2(*(__half2*)&h);
            float l0 = v0 - hf.x, l1 = v1 - hf.y;
            uint32_t l;
            asm("cvt.rn.f16x2.f32 %0, %1, %2;" : "=r"(l) : "f"(l1), "f"(l0));
            hp[q] = h; lp[q] = l;
        }
        *(uint4*)(Ah + g * 8) = HP;
        *(uint4*)(Al + g * 8) = LP;
    }
}

// ===================== PTX helpers =====================

__device__ __forceinline__ uint32_t smem_u32(const void* p) {
    uint32_t a;
    asm("{ .reg .u64 t; cvta.to.shared.u64 t, %1; cvt.u32.u64 %0, t; }" : "=r"(a) : "l"(p));
    return a;
}

__device__ __forceinline__ void ldsm4(uint32_t* r, uint32_t addr) {
    asm volatile("ldmatrix.sync.aligned.m8n8.x4.shared.b16 {%0,%1,%2,%3}, [%4];"
                 : "=r"(r[0]), "=r"(r[1]), "=r"(r[2]), "=r"(r[3]) : "r"(addr));
}

__device__ __forceinline__ void mma_f16(float* d, const uint32_t* a, const uint32_t* b) {
    asm volatile(
        "mma.sync.aligned.m16n8k16.row.col.f32.f16.f16.f32 "
        "{%0,%1,%2,%3}, {%4,%5,%6,%7}, {%8,%9}, {%0,%1,%2,%3};"
        : "+f"(d[0]), "+f"(d[1]), "+f"(d[2]), "+f"(d[3])
        : "r"(a[0]), "r"(a[1]), "r"(a[2]), "r"(a[3]), "r"(b[0]), "r"(b[1]));
}

__device__ __forceinline__ void cp16(uint32_t dst, const void* src) {
    asm volatile("cp.async.cg.shared.global [%0], [%1], 16;" :: "r"(dst), "l"(src) : "memory");
}

// ===================== main GEMM kernel =====================
// SMEM per stage (49152 B): Ah 128x64 fp16 (16K) | Al (+16384) | B (+32768)
// Rows are 128B with SW128 XOR swizzle: chunk' = chunk ^ (row & 7)
#define STAGE_B 49152
#define SMEM_BYTES (NSTAGE * STAGE_B)

__global__ void __launch_bounds__(THREADS, 1)
k_main(const float* __restrict__ bias, float* __restrict__ out) {
    extern __shared__ char sm[];
    const uint32_t sb = smem_u32(sm);
    const int tid = threadIdx.x;
    const int lane = tid & 31;
    const int wid = tid >> 5;
    const int warp_m = wid & 3;       // 4 warps along M
    const int warp_n = wid >> 2;      // 2 warps along N
    const int n0 = blockIdx.x * BN;
    const int m0 = blockIdx.y * BM;

    float acc[2][8][4];
    #pragma unroll
    for (int a = 0; a < 2; ++a)
        #pragma unroll
        for (int b = 0; b < 8; ++b)
            #pragma unroll
            for (int c = 0; c < 4; ++c) acc[a][b][c] = 0.0f;

    // ---- cp.async staging: thread t covers 16B chunks g = t + i*256 ----
    // g in [0,1024): row r = g>>3, chunk ch = g&7
    auto load_stage = [&](int s, int c) {
        const uint32_t base = sb + (uint32_t)(s * STAGE_B);
        const size_t kbyte = (size_t)c * BK;                 // k offset (halves)
        #pragma unroll
        for (int i = 0; i < 4; ++i) {
            int g = tid + i * 256;
            int r = g >> 3, ch = g & 7;
            uint32_t doff = (uint32_t)(r * 128 + (((ch ^ (r & 7))) << 4));
            const __half* srcA = g_Ah + (size_t)(m0 + r) * NFEAT + kbyte + ch * 8;
            const __half* srcL = g_Al + (size_t)(m0 + r) * NFEAT + kbyte + ch * 8;
            const __half* srcB = g_Wt + (size_t)(n0 + r) * NFEAT + kbyte + ch * 8;
            cp16(base + doff, srcA);
            cp16(base + 16384 + doff, srcL);
            cp16(base + 32768 + doff, srcB);
        }
    };

    // ldmatrix per-lane constants
    const uint32_t sel = (uint32_t)(lane & 7);
    const uint32_t a_rowoff = (uint32_t)((warp_m * 32 + (lane & 15)) * 128);
    const uint32_t a_ch = (uint32_t)(lane >> 4);
    const uint32_t b_rowoff = (uint32_t)((warp_n * 64 + ((lane >> 4) << 3) + (lane & 7)) * 128);
    const uint32_t b_ch = (uint32_t)((lane >> 3) & 1);

    auto compute = [&](int s) {
        const uint32_t base = sb + (uint32_t)(s * STAGE_B);
        #pragma unroll
        for (int ks = 0; ks < 4; ++ks) {
            uint32_t Afh[2][4], Afl[2][4], Bf[4][4];
            const uint32_t ach = (((uint32_t)(ks * 2) + a_ch) ^ sel) << 4;
            const uint32_t bch = (((uint32_t)(ks * 2) + b_ch) ^ sel) << 4;
            #pragma unroll
            for (int mt = 0; mt < 2; ++mt) {
                uint32_t ao = a_rowoff + (uint32_t)(mt * 16 * 128) + ach;
                ldsm4(Afh[mt], base + ao);
                ldsm4(Afl[mt], base + 16384 + ao);
            }
            #pragma unroll
            for (int np = 0; np < 4; ++np) {
                uint32_t bo = b_rowoff + (uint32_t)(np * 16 * 128) + bch;
                ldsm4(Bf[np], base + 32768 + bo);
            }
            #pragma unroll
            for (int mt = 0; mt < 2; ++mt)
                #pragma unroll
                for (int np = 0; np < 4; ++np)
                    #pragma unroll
                    for (int h2 = 0; h2 < 2; ++h2) {
                        int nt = np * 2 + h2;
                        mma_f16(acc[mt][nt], Afh[mt], &Bf[np][h2 * 2]);
                        mma_f16(acc[mt][nt], Afl[mt], &Bf[np][h2 * 2]);
                    }
        }
    };

    // ---- 3-stage pipeline, 1 sync per chunk ----
    load_stage(0, 0);
    asm volatile("cp.async.commit_group;" ::: "memory");
    load_stage(1, 1);
    asm volatile("cp.async.commit_group;" ::: "memory");

    #pragma unroll 1
    for (int c = 0; c < NCHUNK; ++c) {
        asm volatile("cp.async.wait_group 1;" ::: "memory");
        __syncthreads();
        compute(c % 3);
        if (c + 2 < NCHUNK) load_stage((c + 2) % 3, c + 2);
        asm volatile("cp.async.commit_group;" ::: "memory");
    }

    // ---- epilogue ----
    const int gid = lane >> 2, tig = lane & 3;
    #pragma unroll
    for (int mt = 0; mt < 2; ++mt) {
        #pragma unroll
        for (int nt = 0; nt < 8; ++nt) {
            int row = m0 + warp_m * 32 + mt * 16 + gid;
            int col = n0 + warp_n * 64 + nt * 8 + tig * 2;
            float b0 = bias[col], b1 = bias[col + 1];
            float2 v0 = {acc[mt][nt][0] + b0, acc[mt][nt][1] + b1};
            float2 v1 = {acc[mt][nt][2] + b0, acc[mt][nt][3] + b1};
            *(float2*)(out + (size_t)row * NOUT + col) = v0;
            *(float2*)(out + (size_t)(row + 8) * NOUT + col) = v1;
        }
    }
}

// ===================== launcher =====================

extern "C" void kernel_launch(void* const* d_in, const int* in_sizes, int n_in,
                              void* d_out, int out_size) {
    const float* x = (const float*)d_in[0];
    const float* w = (const float*)d_in[1];
    const float* b = (const float*)d_in[2];
    float* out = (float*)d_out;

    cudaFuncSetAttribute(k_main, cudaFuncAttributeMaxDynamicSharedMemorySize, SMEM_BYTES);

    k_tab<<<(NFEAT + 255) / 256, 256>>>();
    k_wt<<<dim3(NFEAT / 64, NOUT / 64), 256>>>(w);
    k_expand<<<BATCH, 256>>>(x);
    k_main<<<dim3(NOUT / BN, BATCH / BM), THREADS, SMEM_BYTES>>>(b, out);
}

// round 4
// speedup vs baseline: 4.2656x; 1.7245x over previous
#include <cuda_runtime.h>
#include <cuda_fp16.h>
#include <stdint.h>

#define BATCH 16384
#define NIN   128
#define NFEAT 8384
#define NOUT  512

#define BM 128
#define BN 128
#define BK 64
#define NCHUNK (NFEAT / BK)   // 131
#define THREADS 256
#define NSTAGE 3

// ---- global scratch (static __device__, no allocs) ----
__device__ __align__(16) __half g_A[(size_t)BATCH * NFEAT];    // expanded features fp16 (274.7MB)
__device__ __align__(16) __half g_Wt[(size_t)NOUT * NFEAT];    // W^T fp16 [n][k]
__device__ __align__(16) unsigned short g_tab[NFEAT];          // i | (j<<8); j=128 => linear

// ===================== prep kernels =====================

__global__ void k_tab() {
    int f = blockIdx.x * 256 + threadIdx.x;
    if (f >= NFEAT) return;
    int i, j;
    if (f < NIN) { i = f; j = NIN; }  // linear term: x[i] * 1.0
    else {
        int t = f - NIN;
        i = 0;
        while (NIN * (i + 1) - (i + 1) * i / 2 <= t) i++;
        j = i + (t - (NIN * i - i * (i - 1) / 2));
    }
    g_tab[f] = (unsigned short)(i | (j << 8));
}

// transpose W [8384,512] f32 -> Wt [512,8384] fp16
__global__ void k_wt(const float* __restrict__ W) {
    __shared__ float sm[64][65];
    int k0 = blockIdx.x * 64, n0 = blockIdx.y * 64;
    int tid = threadIdx.x;
    for (int idx = tid; idx < 64 * 64; idx += 256) {
        int r = idx >> 6, c = idx & 63;           // r: k-local, c: n-local
        sm[c][r] = W[(size_t)(k0 + r) * NOUT + n0 + c];
    }
    __syncthreads();
    for (int idx = tid; idx < 64 * 32; idx += 256) {
        int nl = idx >> 5, kl = (idx & 31) * 2;
        float v0 = sm[nl][kl], v1 = sm[nl][kl + 1];
        uint32_t h;
        asm("cvt.rn.f16x2.f32 %0, %1, %2;" : "=r"(h) : "f"(v1), "f"(v0));
        size_t o = (size_t)(n0 + nl) * NFEAT + k0 + kl;   // even
        *(uint32_t*)((unsigned short*)g_Wt + o) = h;
    }
}

// expand X -> fp16 feature matrix [BATCH][NFEAT]
__global__ void __launch_bounds__(256, 4) k_expand(const float* __restrict__ X) {
    __shared__ float xs[129];
    const int b = blockIdx.x;
    const int tid = threadIdx.x;
    if (tid < 128) xs[tid] = X[(size_t)b * NIN + tid];
    if (tid == 0) xs[128] = 1.0f;
    __syncthreads();

    __half* A = g_A + (size_t)b * NFEAT;
    #pragma unroll 1
    for (int g = tid; g < NFEAT / 8; g += 256) {       // 1048 groups of 8 feats
        uint4 tv = *(const uint4*)&g_tab[g * 8];
        uint32_t tw[4] = {tv.x, tv.y, tv.z, tv.w};
        uint4 HP;
        uint32_t* hp = (uint32_t*)&HP;
        #pragma unroll
        for (int q = 0; q < 4; ++q) {
            uint32_t wv = tw[q];
            int i0 = wv & 255, j0 = (wv >> 8) & 255;
            int i1 = (wv >> 16) & 255, j1 = (wv >> 24) & 255;
            float v0 = xs[i0] * xs[j0];
            float v1 = xs[i1] * xs[j1];
            uint32_t h;
            asm("cvt.rn.f16x2.f32 %0, %1, %2;" : "=r"(h) : "f"(v1), "f"(v0));
            hp[q] = h;
        }
        *(uint4*)(A + g * 8) = HP;
    }
}

// ===================== PTX helpers =====================

__device__ __forceinline__ uint32_t smem_u32(const void* p) {
    uint32_t a;
    asm("{ .reg .u64 t; cvta.to.shared.u64 t, %1; cvt.u32.u64 %0, t; }" : "=r"(a) : "l"(p));
    return a;
}

__device__ __forceinline__ void ldsm4(uint32_t* r, uint32_t addr) {
    asm volatile("ldmatrix.sync.aligned.m8n8.x4.shared.b16 {%0,%1,%2,%3}, [%4];"
                 : "=r"(r[0]), "=r"(r[1]), "=r"(r[2]), "=r"(r[3]) : "r"(addr));
}

__device__ __forceinline__ void mma_f16(float* d, const uint32_t* a, const uint32_t* b) {
    asm volatile(
        "mma.sync.aligned.m16n8k16.row.col.f32.f16.f16.f32 "
        "{%0,%1,%2,%3}, {%4,%5,%6,%7}, {%8,%9}, {%0,%1,%2,%3};"
        : "+f"(d[0]), "+f"(d[1]), "+f"(d[2]), "+f"(d[3])
        : "r"(a[0]), "r"(a[1]), "r"(a[2]), "r"(a[3]), "r"(b[0]), "r"(b[1]));
}

__device__ __forceinline__ void cp16(uint32_t dst, const void* src) {
    asm volatile("cp.async.cg.shared.global [%0], [%1], 16;" :: "r"(dst), "l"(src) : "memory");
}

// ===================== main GEMM kernel =====================
// SMEM per stage (32768 B): A 128x64 fp16 (16K) | B (+16384)
// Rows are 128B with SW128 XOR swizzle: chunk' = chunk ^ (row & 7)
#define STAGE_B 32768
#define SMEM_BYTES (NSTAGE * STAGE_B)   // 98304 -> 2 CTAs/SM

__global__ void __launch_bounds__(THREADS, 2)
k_main(const float* __restrict__ bias, float* __restrict__ out) {
    extern __shared__ char sm[];
    const uint32_t sb = smem_u32(sm);
    const int tid = threadIdx.x;
    const int lane = tid & 31;
    const int wid = tid >> 5;
    const int warp_m = wid & 3;       // 4 warps along M
    const int warp_n = wid >> 2;      // 2 warps along N
    const int n0 = blockIdx.x * BN;
    const int m0 = blockIdx.y * BM;

    float acc[2][8][4];
    #pragma unroll
    for (int a = 0; a < 2; ++a)
        #pragma unroll
        for (int b = 0; b < 8; ++b)
            #pragma unroll
            for (int c = 0; c < 4; ++c) acc[a][b][c] = 0.0f;

    // ---- cp.async staging: thread t covers 16B chunks g = t + i*256 ----
    // g in [0,1024): row r = g>>3, chunk ch = g&7; A and B both
    auto load_stage = [&](int s, int c) {
        const uint32_t base = sb + (uint32_t)(s * STAGE_B);
        const size_t koff = (size_t)c * BK;
        #pragma unroll
        for (int i = 0; i < 4; ++i) {
            int g = tid + i * 256;
            int r = g >> 3, ch = g & 7;
            uint32_t doff = (uint32_t)(r * 128 + (((ch ^ (r & 7))) << 4));
            cp16(base + doff,         g_A  + (size_t)(m0 + r) * NFEAT + koff + ch * 8);
            cp16(base + 16384 + doff, g_Wt + (size_t)(n0 + r) * NFEAT + koff + ch * 8);
        }
    };

    // ldmatrix per-lane constants
    const uint32_t sel = (uint32_t)(lane & 7);
    const uint32_t a_rowoff = (uint32_t)((warp_m * 32 + (lane & 15)) * 128);
    const uint32_t a_ch = (uint32_t)(lane >> 4);
    const uint32_t b_rowoff = (uint32_t)((warp_n * 64 + ((lane >> 4) << 3) + (lane & 7)) * 128);
    const uint32_t b_ch = (uint32_t)((lane >> 3) & 1);

    auto compute = [&](int s) {
        const uint32_t base = sb + (uint32_t)(s * STAGE_B);
        #pragma unroll
        for (int ks = 0; ks < 4; ++ks) {
            uint32_t Af[2][4], Bf[4][4];
            const uint32_t ach = (((uint32_t)(ks * 2) + a_ch) ^ sel) << 4;
            const uint32_t bch = (((uint32_t)(ks * 2) + b_ch) ^ sel) << 4;
            #pragma unroll
            for (int mt = 0; mt < 2; ++mt)
                ldsm4(Af[mt], base + a_rowoff + (uint32_t)(mt * 16 * 128) + ach);
            #pragma unroll
            for (int np = 0; np < 4; ++np)
                ldsm4(Bf[np], base + 16384 + b_rowoff + (uint32_t)(np * 16 * 128) + bch);
            #pragma unroll
            for (int mt = 0; mt < 2; ++mt)
                #pragma unroll
                for (int np = 0; np < 4; ++np)
                    #pragma unroll
                    for (int h2 = 0; h2 < 2; ++h2)
                        mma_f16(acc[mt][np * 2 + h2], Af[mt], &Bf[np][h2 * 2]);
        }
    };

    // ---- 3-stage pipeline, 1 sync per chunk; loads issued before compute ----
    load_stage(0, 0);
    asm volatile("cp.async.commit_group;" ::: "memory");
    load_stage(1, 1);
    asm volatile("cp.async.commit_group;" ::: "memory");

    #pragma unroll 1
    for (int c = 0; c < NCHUNK; ++c) {
        asm volatile("cp.async.wait_group 1;" ::: "memory");
        __syncthreads();
        if (c + 2 < NCHUNK) load_stage((c + 2) % 3, c + 2);
        asm volatile("cp.async.commit_group;" ::: "memory");
        compute(c % 3);
    }

    // ---- epilogue ----
    const int gid = lane >> 2, tig = lane & 3;
    #pragma unroll
    for (int mt = 0; mt < 2; ++mt) {
        #pragma unroll
        for (int nt = 0; nt < 8; ++nt) {
            int row = m0 + warp_m * 32 + mt * 16 + gid;
            int col = n0 + warp_n * 64 + nt * 8 + tig * 2;
            float b0 = bias[col], b1 = bias[col + 1];
            float2 v0 = {acc[mt][nt][0] + b0, acc[mt][nt][1] + b1};
            float2 v1 = {acc[mt][nt][2] + b0, acc[mt][nt][3] + b1};
            *(float2*)(out + (size_t)row * NOUT + col) = v0;
            *(float2*)(out + (size_t)(row + 8) * NOUT + col) = v1;
        }
    }
}

// ===================== launcher =====================

extern "C" void kernel_launch(void* const* d_in, const int* in_sizes, int n_in,
                              void* d_out, int out_size) {
    const float* x = (const float*)d_in[0];
    const float* w = (const float*)d_in[1];
    const float* b = (const float*)d_in[2];
    float* out = (float*)d_out;

    cudaFuncSetAttribute(k_main, cudaFuncAttributeMaxDynamicSharedMemorySize, SMEM_BYTES);

    k_tab<<<(NFEAT + 255) / 256, 256>>>();
    k_wt<<<dim3(NFEAT / 64, NOUT / 64), 256>>>(w);
    k_expand<<<BATCH, 256>>>(x);
    k_main<<<dim3(NOUT / BN, BATCH / BM), THREADS, SMEM_BYTES>>>(b, out);
}

// round 5
// speedup vs baseline: 4.3474x; 1.0192x over previous
#include <cuda_runtime.h>
#include <cuda_fp16.h>
#include <stdint.h>

#define BATCH 16384
#define NIN   128
#define NFEAT 8384
#define NOUT  512

#define BM 128
#define BN 128
#define BK 64
#define NCHUNK (NFEAT / BK)   // 131
#define THREADS 128
#define NSTAGE 3

// ---- global scratch (static __device__, no allocs) ----
__device__ __align__(16) __half g_A[(size_t)BATCH * NFEAT];    // expanded features fp16 (274.7MB)
__device__ __align__(16) __half g_Wt[(size_t)NOUT * NFEAT];    // W^T fp16 [n][k]
__device__ __align__(16) unsigned short g_tab[NFEAT];          // i | (j<<8); j=128 => linear

// ===================== prep kernels =====================

__global__ void k_tab() {
    int f = blockIdx.x * 256 + threadIdx.x;
    if (f >= NFEAT) return;
    int i, j;
    if (f < NIN) { i = f; j = NIN; }  // linear term: x[i] * 1.0
    else {
        int t = f - NIN;
        i = 0;
        while (NIN * (i + 1) - (i + 1) * i / 2 <= t) i++;
        j = i + (t - (NIN * i - i * (i - 1) / 2));
    }
    g_tab[f] = (unsigned short)(i | (j << 8));
}

// transpose W [8384,512] f32 -> Wt [512,8384] fp16
__global__ void k_wt(const float* __restrict__ W) {
    __shared__ float sm[64][65];
    int k0 = blockIdx.x * 64, n0 = blockIdx.y * 64;
    int tid = threadIdx.x;
    for (int idx = tid; idx < 64 * 64; idx += 256) {
        int r = idx >> 6, c = idx & 63;           // r: k-local, c: n-local
        sm[c][r] = W[(size_t)(k0 + r) * NOUT + n0 + c];
    }
    __syncthreads();
    for (int idx = tid; idx < 64 * 32; idx += 256) {
        int nl = idx >> 5, kl = (idx & 31) * 2;
        float v0 = sm[nl][kl], v1 = sm[nl][kl + 1];
        uint32_t h;
        asm("cvt.rn.f16x2.f32 %0, %1, %2;" : "=r"(h) : "f"(v1), "f"(v0));
        size_t o = (size_t)(n0 + nl) * NFEAT + k0 + kl;   // even
        *(uint32_t*)((unsigned short*)g_Wt + o) = h;
    }
}

// expand X -> fp16 feature matrix [BATCH][NFEAT]
__global__ void __launch_bounds__(256, 4) k_expand(const float* __restrict__ X) {
    __shared__ float xs[129];
    const int b = blockIdx.x;
    const int tid = threadIdx.x;
    if (tid < 128) xs[tid] = X[(size_t)b * NIN + tid];
    if (tid == 0) xs[128] = 1.0f;
    __syncthreads();

    __half* A = g_A + (size_t)b * NFEAT;
    #pragma unroll 1
    for (int g = tid; g < NFEAT / 8; g += 256) {       // 1048 groups of 8 feats
        uint4 tv = *(const uint4*)&g_tab[g * 8];
        uint32_t tw[4] = {tv.x, tv.y, tv.z, tv.w};
        uint4 HP;
        uint32_t* hp = (uint32_t*)&HP;
        #pragma unroll
        for (int q = 0; q < 4; ++q) {
            uint32_t wv = tw[q];
            int i0 = wv & 255, j0 = (wv >> 8) & 255;
            int i1 = (wv >> 16) & 255, j1 = (wv >> 24) & 255;
            float v0 = xs[i0] * xs[j0];
            float v1 = xs[i1] * xs[j1];
            uint32_t h;
            asm("cvt.rn.f16x2.f32 %0, %1, %2;" : "=r"(h) : "f"(v1), "f"(v0));
            hp[q] = h;
        }
        *(uint4*)(A + g * 8) = HP;
    }
}

// ===================== PTX helpers =====================

__device__ __forceinline__ uint32_t smem_u32(const void* p) {
    uint32_t a;
    asm("{ .reg .u64 t; cvta.to.shared.u64 t, %1; cvt.u32.u64 %0, t; }" : "=r"(a) : "l"(p));
    return a;
}

__device__ __forceinline__ void ldsm4(uint32_t* r, uint32_t addr) {
    asm volatile("ldmatrix.sync.aligned.m8n8.x4.shared.b16 {%0,%1,%2,%3}, [%4];"
                 : "=r"(r[0]), "=r"(r[1]), "=r"(r[2]), "=r"(r[3]) : "r"(addr));
}

__device__ __forceinline__ void mma_f16(float* d, const uint32_t* a, const uint32_t* b) {
    asm volatile(
        "mma.sync.aligned.m16n8k16.row.col.f32.f16.f16.f32 "
        "{%0,%1,%2,%3}, {%4,%5,%6,%7}, {%8,%9}, {%0,%1,%2,%3};"
        : "+f"(d[0]), "+f"(d[1]), "+f"(d[2]), "+f"(d[3])
        : "r"(a[0]), "r"(a[1]), "r"(a[2]), "r"(a[3]), "r"(b[0]), "r"(b[1]));
}

__device__ __forceinline__ void cp16(uint32_t dst, const void* src) {
    asm volatile("cp.async.cg.shared.global [%0], [%1], 16;" :: "r"(dst), "l"(src) : "memory");
}

// ===================== main GEMM kernel =====================
// 4 warps, each owning a 64x64 output tile (mt=4 x n8=8).
// SMEM per stage (32768 B): A 128x64 fp16 (16K) | B (+16384)
// Rows are 128B with SW128 XOR swizzle: chunk' = chunk ^ (row & 7)
#define STAGE_B 32768
#define SMEM_BYTES (NSTAGE * STAGE_B)   // 98304 -> 2 CTAs/SM

__global__ void __launch_bounds__(THREADS, 2)
k_main(const float* __restrict__ bias, float* __restrict__ out) {
    extern __shared__ char sm[];
    const uint32_t sb = smem_u32(sm);
    const int tid = threadIdx.x;
    const int lane = tid & 31;
    const int wid = tid >> 5;
    const int warp_m = wid & 1;       // 2 warps along M (64 rows each)
    const int warp_n = wid >> 1;      // 2 warps along N (64 cols each)
    const int n0 = blockIdx.x * BN;
    const int m0 = blockIdx.y * BM;

    float acc[4][8][4];
    #pragma unroll
    for (int a = 0; a < 4; ++a)
        #pragma unroll
        for (int b = 0; b < 8; ++b)
            #pragma unroll
            for (int c = 0; c < 4; ++c) acc[a][b][c] = 0.0f;

    // ---- cp.async staging: 1024 16B chunks each for A and B, 128 threads ----
    auto load_stage = [&](int s, int c) {
        const uint32_t base = sb + (uint32_t)(s * STAGE_B);
        const size_t koff = (size_t)c * BK;
        #pragma unroll
        for (int i = 0; i < 8; ++i) {
            int g = tid + i * 128;
            int r = g >> 3, ch = g & 7;
            uint32_t doff = (uint32_t)(r * 128 + (((ch ^ (r & 7))) << 4));
            cp16(base + doff,         g_A  + (size_t)(m0 + r) * NFEAT + koff + ch * 8);
            cp16(base + 16384 + doff, g_Wt + (size_t)(n0 + r) * NFEAT + koff + ch * 8);
        }
    };

    // ldmatrix per-lane constants
    const uint32_t sel = (uint32_t)(lane & 7);
    const uint32_t a_rowoff = (uint32_t)((warp_m * 64 + (lane & 15)) * 128);
    const uint32_t a_ch = (uint32_t)(lane >> 4);
    const uint32_t b_rowoff = (uint32_t)((warp_n * 64 + ((lane >> 4) << 3) + (lane & 7)) * 128);
    const uint32_t b_ch = (uint32_t)((lane >> 3) & 1);

    auto compute = [&](int s) {
        const uint32_t base = sb + (uint32_t)(s * STAGE_B);
        #pragma unroll
        for (int ks = 0; ks < 4; ++ks) {
            uint32_t Af[4][4], Bf[4][4];
            const uint32_t ach = (((uint32_t)(ks * 2) + a_ch) ^ sel) << 4;
            const uint32_t bch = (((uint32_t)(ks * 2) + b_ch) ^ sel) << 4;
            #pragma unroll
            for (int mt = 0; mt < 4; ++mt)
                ldsm4(Af[mt], base + a_rowoff + (uint32_t)(mt * 16 * 128) + ach);
            #pragma unroll
            for (int np = 0; np < 4; ++np)
                ldsm4(Bf[np], base + 16384 + b_rowoff + (uint32_t)(np * 16 * 128) + bch);
            #pragma unroll
            for (int mt = 0; mt < 4; ++mt)
                #pragma unroll
                for (int np = 0; np < 4; ++np)
                    #pragma unroll
                    for (int h2 = 0; h2 < 2; ++h2)
                        mma_f16(acc[mt][np * 2 + h2], Af[mt], &Bf[np][h2 * 2]);
        }
    };

    // ---- 3-stage pipeline, 1 sync per chunk; loads issued before compute ----
    load_stage(0, 0);
    asm volatile("cp.async.commit_group;" ::: "memory");
    load_stage(1, 1);
    asm volatile("cp.async.commit_group;" ::: "memory");

    #pragma unroll 1
    for (int c = 0; c < NCHUNK; ++c) {
        asm volatile("cp.async.wait_group 1;" ::: "memory");
        __syncthreads();
        if (c + 2 < NCHUNK) load_stage((c + 2) % 3, c + 2);
        asm volatile("cp.async.commit_group;" ::: "memory");
        compute(c % 3);
    }

    // ---- epilogue ----
    const int gid = lane >> 2, tig = lane & 3;
    #pragma unroll
    for (int mt = 0; mt < 4; ++mt) {
        #pragma unroll
        for (int nt = 0; nt < 8; ++nt) {
            int row = m0 + warp_m * 64 + mt * 16 + gid;
            int col = n0 + warp_n * 64 + nt * 8 + tig * 2;
            float b0 = bias[col], b1 = bias[col + 1];
            float2 v0 = {acc[mt][nt][0] + b0, acc[mt][nt][1] + b1};
            float2 v1 = {acc[mt][nt][2] + b0, acc[mt][nt][3] + b1};
            *(float2*)(out + (size_t)row * NOUT + col) = v0;
            *(float2*)(out + (size_t)(row + 8) * NOUT + col) = v1;
        }
    }
}

// ===================== launcher =====================

extern "C" void kernel_launch(void* const* d_in, const int* in_sizes, int n_in,
                              void* d_out, int out_size) {
    const float* x = (const float*)d_in[0];
    const float* w = (const float*)d_in[1];
    const float* b = (const float*)d_in[2];
    float* out = (float*)d_out;

    cudaFuncSetAttribute(k_main, cudaFuncAttributeMaxDynamicSharedMemorySize, SMEM_BYTES);

    k_tab<<<(NFEAT + 255) / 256, 256>>>();
    k_wt<<<dim3(NFEAT / 64, NOUT / 64), 256>>>(w);
    k_expand<<<BATCH, 256>>>(x);
    k_main<<<dim3(NOUT / BN, BATCH / BM), THREADS, SMEM_BYTES>>>(b, out);
}

// round 6
// speedup vs baseline: 4.7475x; 1.0920x over previous
#include <cuda_runtime.h>
#include <cuda_fp16.h>
#include <stdint.h>

#define BATCH 16384
#define NIN   128
#define NFEAT 8384
#define NOUT  512

#define BM 128
#define BN 128
#define BK 64
#define NCHUNK (NFEAT / BK)   // 131
#define THREADS 128
#define NSTAGE 3

// ---- global scratch (static __device__, no allocs) ----
__device__ __align__(16) __half g_A[(size_t)BATCH * NFEAT];    // expanded features fp16 (274.7MB)
__device__ __align__(16) __half g_Wt[(size_t)NOUT * NFEAT];    // W^T fp16 [n][k]
__device__ __align__(16) unsigned short g_tab[NFEAT];          // i | (j<<8); j=128 => linear

// ===================== prep kernels =====================

__global__ void k_tab() {
    int f = blockIdx.x * 256 + threadIdx.x;
    if (f >= NFEAT) return;
    int i, j;
    if (f < NIN) { i = f; j = NIN; }  // linear term: x[i] * 1.0
    else {
        int t = f - NIN;
        i = 0;
        while (NIN * (i + 1) - (i + 1) * i / 2 <= t) i++;
        j = i + (t - (NIN * i - i * (i - 1) / 2));
    }
    g_tab[f] = (unsigned short)(i | (j << 8));
}

// transpose W [8384,512] f32 -> Wt [512,8384] fp16
__global__ void k_wt(const float* __restrict__ W) {
    __shared__ float sm[64][65];
    int k0 = blockIdx.x * 64, n0 = blockIdx.y * 64;
    int tid = threadIdx.x;
    for (int idx = tid; idx < 64 * 64; idx += 256) {
        int r = idx >> 6, c = idx & 63;           // r: k-local, c: n-local
        sm[c][r] = W[(size_t)(k0 + r) * NOUT + n0 + c];
    }
    __syncthreads();
    for (int idx = tid; idx < 64 * 32; idx += 256) {
        int nl = idx >> 5, kl = (idx & 31) * 2;
        float v0 = sm[nl][kl], v1 = sm[nl][kl + 1];
        uint32_t h;
        asm("cvt.rn.f16x2.f32 %0, %1, %2;" : "=r"(h) : "f"(v1), "f"(v0));
        size_t o = (size_t)(n0 + nl) * NFEAT + k0 + kl;   // even
        *(uint32_t*)((unsigned short*)g_Wt + o) = h;
    }
}

// expand X -> fp16 feature matrix [BATCH][NFEAT]
__global__ void __launch_bounds__(256, 4) k_expand(const float* __restrict__ X) {
    __shared__ float xs[129];
    const int b = blockIdx.x;
    const int tid = threadIdx.x;
    if (tid < 128) xs[tid] = X[(size_t)b * NIN + tid];
    if (tid == 0) xs[128] = 1.0f;
    __syncthreads();

    __half* A = g_A + (size_t)b * NFEAT;
    #pragma unroll 1
    for (int g = tid; g < NFEAT / 8; g += 256) {       // 1048 groups of 8 feats
        uint4 tv = *(const uint4*)&g_tab[g * 8];
        uint32_t tw[4] = {tv.x, tv.y, tv.z, tv.w};
        uint4 HP;
        uint32_t* hp = (uint32_t*)&HP;
        #pragma unroll
        for (int q = 0; q < 4; ++q) {
            uint32_t wv = tw[q];
            int i0 = wv & 255, j0 = (wv >> 8) & 255;
            int i1 = (wv >> 16) & 255, j1 = (wv >> 24) & 255;
            float v0 = xs[i0] * xs[j0];
            float v1 = xs[i1] * xs[j1];
            uint32_t h;
            asm("cvt.rn.f16x2.f32 %0, %1, %2;" : "=r"(h) : "f"(v1), "f"(v0));
            hp[q] = h;
        }
        *(uint4*)(A + g * 8) = HP;
    }
}

// ===================== PTX helpers =====================

__device__ __forceinline__ uint32_t smem_u32(const void* p) {
    uint32_t a;
    asm("{ .reg .u64 t; cvta.to.shared.u64 t, %1; cvt.u32.u64 %0, t; }" : "=r"(a) : "l"(p));
    return a;
}

__device__ __forceinline__ void ldsm4(uint32_t* r, uint32_t addr) {
    asm volatile("ldmatrix.sync.aligned.m8n8.x4.shared.b16 {%0,%1,%2,%3}, [%4];"
                 : "=r"(r[0]), "=r"(r[1]), "=r"(r[2]), "=r"(r[3]) : "r"(addr));
}

__device__ __forceinline__ void mma_f16(float* d, const uint32_t* a, const uint32_t* b) {
    asm volatile(
        "mma.sync.aligned.m16n8k16.row.col.f32.f16.f16.f32 "
        "{%0,%1,%2,%3}, {%4,%5,%6,%7}, {%8,%9}, {%0,%1,%2,%3};"
        : "+f"(d[0]), "+f"(d[1]), "+f"(d[2]), "+f"(d[3])
        : "r"(a[0]), "r"(a[1]), "r"(a[2]), "r"(a[3]), "r"(b[0]), "r"(b[1]));
}

__device__ __forceinline__ void cp16(uint32_t dst, const void* src) {
    asm volatile("cp.async.cg.shared.global [%0], [%1], 16;" :: "r"(dst), "l"(src) : "memory");
}

// ===================== main GEMM kernel =====================
// 4 warps, each owning a 64x64 output tile; register-double-buffered fragments.
// SMEM per stage (32768 B): A 128x64 fp16 (16K) | B (+16384)
// Rows are 128B with SW128 XOR swizzle: chunk' = chunk ^ (row & 7)
#define STAGE_B 32768
#define SMEM_BYTES (NSTAGE * STAGE_B)   // 98304 -> 2 CTAs/SM

__global__ void __launch_bounds__(THREADS, 2)
k_main(const float* __restrict__ bias, float* __restrict__ out) {
    extern __shared__ char sm[];
    const uint32_t sb = smem_u32(sm);
    const int tid = threadIdx.x;
    const int lane = tid & 31;
    const int wid = tid >> 5;
    const int warp_m = wid & 1;       // 2 warps along M (64 rows each)
    const int warp_n = wid >> 1;      // 2 warps along N (64 cols each)
    const int n0 = blockIdx.x * BN;
    const int m0 = blockIdx.y * BM;

    float acc[4][8][4];
    #pragma unroll
    for (int a = 0; a < 4; ++a)
        #pragma unroll
        for (int b = 0; b < 8; ++b)
            #pragma unroll
            for (int c = 0; c < 4; ++c) acc[a][b][c] = 0.0f;

    // ---- cp.async staging: 1024 16B chunks each for A and B, 128 threads ----
    auto load_stage = [&](int s, int c) {
        const uint32_t base = sb + (uint32_t)(s * STAGE_B);
        const size_t koff = (size_t)c * BK;
        #pragma unroll
        for (int i = 0; i < 8; ++i) {
            int g = tid + i * 128;
            int r = g >> 3, ch = g & 7;
            uint32_t doff = (uint32_t)(r * 128 + (((ch ^ (r & 7))) << 4));
            cp16(base + doff,         g_A  + (size_t)(m0 + r) * NFEAT + koff + ch * 8);
            cp16(base + 16384 + doff, g_Wt + (size_t)(n0 + r) * NFEAT + koff + ch * 8);
        }
    };

    // ldmatrix per-lane constants
    const uint32_t sel = (uint32_t)(lane & 7);
    const uint32_t a_rowoff = (uint32_t)((warp_m * 64 + (lane & 15)) * 128);
    const uint32_t a_ch = (uint32_t)(lane >> 4);
    const uint32_t b_rowoff = (uint32_t)((warp_n * 64 + ((lane >> 4) << 3) + (lane & 7)) * 128);
    const uint32_t b_ch = (uint32_t)((lane >> 3) & 1);

    uint32_t Af[2][4][4], Bf[2][4][4];   // register double buffer

    auto load_frags = [&](uint32_t base, int ks, int buf) {
        const uint32_t ach = (((uint32_t)(ks * 2) + a_ch) ^ sel) << 4;
        const uint32_t bch = (((uint32_t)(ks * 2) + b_ch) ^ sel) << 4;
        #pragma unroll
        for (int mt = 0; mt < 4; ++mt)
            ldsm4(Af[buf][mt], base + a_rowoff + (uint32_t)(mt * 16 * 128) + ach);
        #pragma unroll
        for (int np = 0; np < 4; ++np)
            ldsm4(Bf[buf][np], base + 16384 + b_rowoff + (uint32_t)(np * 16 * 128) + bch);
    };

    auto mma_step = [&](int buf) {
        #pragma unroll
        for (int mt = 0; mt < 4; ++mt)
            #pragma unroll
            for (int np = 0; np < 4; ++np)
                #pragma unroll
                for (int h2 = 0; h2 < 2; ++h2)
                    mma_f16(acc[mt][np * 2 + h2], Af[buf][mt], &Bf[buf][np][h2 * 2]);
    };

    // ---- 3-stage cp.async pipeline + in-chunk register pipelining ----
    load_stage(0, 0);
    asm volatile("cp.async.commit_group;" ::: "memory");
    load_stage(1, 1);
    asm volatile("cp.async.commit_group;" ::: "memory");

    #pragma unroll 1
    for (int c = 0; c < NCHUNK; ++c) {
        asm volatile("cp.async.wait_group 1;" ::: "memory");
        __syncthreads();
        const uint32_t base = sb + (uint32_t)((c % 3) * STAGE_B);
        load_frags(base, 0, 0);                 // prologue for this chunk
        if (c + 2 < NCHUNK) load_stage((c + 2) % 3, c + 2);
        asm volatile("cp.async.commit_group;" ::: "memory");
        #pragma unroll
        for (int ks = 0; ks < 4; ++ks) {
            int cur = ks & 1;
            if (ks < 3) load_frags(base, ks + 1, cur ^ 1);   // prefetch next k-step
            mma_step(cur);
        }
    }

    // ---- epilogue ----
    const int gid = lane >> 2, tig = lane & 3;
    #pragma unroll
    for (int mt = 0; mt < 4; ++mt) {
        #pragma unroll
        for (int nt = 0; nt < 8; ++nt) {
            int row = m0 + warp_m * 64 + mt * 16 + gid;
            int col = n0 + warp_n * 64 + nt * 8 + tig * 2;
            float b0 = bias[col], b1 = bias[col + 1];
            float2 v0 = {acc[mt][nt][0] + b0, acc[mt][nt][1] + b1};
            float2 v1 = {acc[mt][nt][2] + b0, acc[mt][nt][3] + b1};
            *(float2*)(out + (size_t)row * NOUT + col) = v0;
            *(float2*)(out + (size_t)(row + 8) * NOUT + col) = v1;
        }
    }
}

// ===================== launcher =====================

extern "C" void kernel_launch(void* const* d_in, const int* in_sizes, int n_in,
                              void* d_out, int out_size) {
    const float* x = (const float*)d_in[0];
    const float* w = (const float*)d_in[1];
    const float* b = (const float*)d_in[2];
    float* out = (float*)d_out;

    cudaFuncSetAttribute(k_main, cudaFuncAttributeMaxDynamicSharedMemorySize, SMEM_BYTES);

    k_tab<<<(NFEAT + 255) / 256, 256>>>();
    k_wt<<<dim3(NFEAT / 64, NOUT / 64), 256>>>(w);
    k_expand<<<BATCH, 256>>>(x);
    k_main<<<dim3(NOUT / BN, BATCH / BM), THREADS, SMEM_BYTES>>>(b, out);
}

// round 7
// speedup vs baseline: 5.0807x; 1.0702x over previous
#include <cuda_runtime.h>
#include <cuda_fp16.h>
#include <stdint.h>

#define BATCH 16384
#define NIN   128
#define NFEAT 8384
#define NOUT  512

#define BM 128
#define BN 128
#define BK 64
#define NCHUNK (NFEAT / BK)   // 131
#define THREADS 128
#define NSTAGE 3

// ---- global scratch (static __device__, no allocs) ----
__device__ __align__(16) __half g_A[(size_t)BATCH * NFEAT];    // expanded features fp16 (274.7MB)
__device__ __align__(16) __half g_Wt[(size_t)NOUT * NFEAT];    // W^T fp16 [n][k]
__device__ __align__(16) unsigned short g_tab[NFEAT];          // i | (j<<8); j=128 => linear

// ===================== prep kernels =====================

__global__ void k_tab() {
    int f = blockIdx.x * 256 + threadIdx.x;
    if (f >= NFEAT) return;
    int i, j;
    if (f < NIN) { i = f; j = NIN; }  // linear term: x[i] * 1.0
    else {
        int t = f - NIN;
        i = 0;
        while (NIN * (i + 1) - (i + 1) * i / 2 <= t) i++;
        j = i + (t - (NIN * i - i * (i - 1) / 2));
    }
    g_tab[f] = (unsigned short)(i | (j << 8));
}

// transpose W [8384,512] f32 -> Wt [512,8384] fp16
__global__ void k_wt(const float* __restrict__ W) {
    __shared__ float sm[64][65];
    int k0 = blockIdx.x * 64, n0 = blockIdx.y * 64;
    int tid = threadIdx.x;
    for (int idx = tid; idx < 64 * 64; idx += 256) {
        int r = idx >> 6, c = idx & 63;           // r: k-local, c: n-local
        sm[c][r] = W[(size_t)(k0 + r) * NOUT + n0 + c];
    }
    __syncthreads();
    for (int idx = tid; idx < 64 * 32; idx += 256) {
        int nl = idx >> 5, kl = (idx & 31) * 2;
        float v0 = sm[nl][kl], v1 = sm[nl][kl + 1];
        uint32_t h;
        asm("cvt.rn.f16x2.f32 %0, %1, %2;" : "=r"(h) : "f"(v1), "f"(v0));
        size_t o = (size_t)(n0 + nl) * NFEAT + k0 + kl;   // even
        *(uint32_t*)((unsigned short*)g_Wt + o) = h;
    }
}

// expand X -> fp16 feature matrix [BATCH][NFEAT]
__global__ void __launch_bounds__(256, 4) k_expand(const float* __restrict__ X) {
    __shared__ float xs[129];
    const int b = blockIdx.x;
    const int tid = threadIdx.x;
    if (tid < 128) xs[tid] = X[(size_t)b * NIN + tid];
    if (tid == 0) xs[128] = 1.0f;
    __syncthreads();

    __half* A = g_A + (size_t)b * NFEAT;
    #pragma unroll 1
    for (int g = tid; g < NFEAT / 8; g += 256) {       // 1048 groups of 8 feats
        uint4 tv = *(const uint4*)&g_tab[g * 8];
        uint32_t tw[4] = {tv.x, tv.y, tv.z, tv.w};
        uint4 HP;
        uint32_t* hp = (uint32_t*)&HP;
        #pragma unroll
        for (int q = 0; q < 4; ++q) {
            uint32_t wv = tw[q];
            int i0 = wv & 255, j0 = (wv >> 8) & 255;
            int i1 = (wv >> 16) & 255, j1 = (wv >> 24) & 255;
            float v0 = xs[i0] * xs[j0];
            float v1 = xs[i1] * xs[j1];
            uint32_t h;
            asm("cvt.rn.f16x2.f32 %0, %1, %2;" : "=r"(h) : "f"(v1), "f"(v0));
            hp[q] = h;
        }
        *(uint4*)(A + g * 8) = HP;
    }
}

// ===================== PTX helpers =====================

__device__ __forceinline__ uint32_t smem_u32(const void* p) {
    uint32_t a;
    asm("{ .reg .u64 t; cvta.to.shared.u64 t, %1; cvt.u32.u64 %0, t; }" : "=r"(a) : "l"(p));
    return a;
}

__device__ __forceinline__ void ldsm4(uint32_t* r, uint32_t addr) {
    asm volatile("ldmatrix.sync.aligned.m8n8.x4.shared.b16 {%0,%1,%2,%3}, [%4];"
                 : "=r"(r[0]), "=r"(r[1]), "=r"(r[2]), "=r"(r[3]) : "r"(addr));
}

__device__ __forceinline__ void mma_f16(float* d, const uint32_t* a, const uint32_t* b) {
    asm volatile(
        "mma.sync.aligned.m16n8k16.row.col.f32.f16.f16.f32 "
        "{%0,%1,%2,%3}, {%4,%5,%6,%7}, {%8,%9}, {%0,%1,%2,%3};"
        : "+f"(d[0]), "+f"(d[1]), "+f"(d[2]), "+f"(d[3])
        : "r"(a[0]), "r"(a[1]), "r"(a[2]), "r"(a[3]), "r"(b[0]), "r"(b[1]));
}

__device__ __forceinline__ void cp16(uint32_t dst, const void* src) {
    asm volatile("cp.async.cg.shared.global [%0], [%1], 16;" :: "r"(dst), "l"(src) : "memory");
}

// ===================== main GEMM kernel =====================
// 4 warps, each owning a 64x64 output tile; cross-chunk register pipelining:
// every chunk is entered with its ks0 fragments already loaded (no ldsm bubble).
// SMEM per stage (32768 B): A 128x64 fp16 (16K) | B (+16384)
// Rows are 128B with SW128 XOR swizzle: chunk' = chunk ^ (row & 7)
#define STAGE_B 32768
#define SMEM_BYTES (NSTAGE * STAGE_B)   // 98304 -> 2 CTAs/SM

__global__ void __launch_bounds__(THREADS, 2)
k_main(const float* __restrict__ bias, float* __restrict__ out) {
    extern __shared__ char sm[];
    const uint32_t sb = smem_u32(sm);
    const int tid = threadIdx.x;
    const int lane = tid & 31;
    const int wid = tid >> 5;
    const int warp_m = wid & 1;       // 2 warps along M (64 rows each)
    const int warp_n = wid >> 1;      // 2 warps along N (64 cols each)
    const int n0 = blockIdx.x * BN;
    const int m0 = blockIdx.y * BM;

    float acc[4][8][4];
    #pragma unroll
    for (int a = 0; a < 4; ++a)
        #pragma unroll
        for (int b = 0; b < 8; ++b)
            #pragma unroll
            for (int c = 0; c < 4; ++c) acc[a][b][c] = 0.0f;

    // ---- cp.async staging: 1024 16B chunks each for A and B, 128 threads ----
    auto load_stage = [&](int s, int c) {
        const uint32_t base = sb + (uint32_t)(s * STAGE_B);
        const size_t koff = (size_t)c * BK;
        #pragma unroll
        for (int i = 0; i < 8; ++i) {
            int g = tid + i * 128;
            int r = g >> 3, ch = g & 7;
            uint32_t doff = (uint32_t)(r * 128 + (((ch ^ (r & 7))) << 4));
            cp16(base + doff,         g_A  + (size_t)(m0 + r) * NFEAT + koff + ch * 8);
            cp16(base + 16384 + doff, g_Wt + (size_t)(n0 + r) * NFEAT + koff + ch * 8);
        }
    };

    // ldmatrix per-lane constants
    const uint32_t sel = (uint32_t)(lane & 7);
    const uint32_t a_rowoff = (uint32_t)((warp_m * 64 + (lane & 15)) * 128);
    const uint32_t a_ch = (uint32_t)(lane >> 4);
    const uint32_t b_rowoff = (uint32_t)((warp_n * 64 + ((lane >> 4) << 3) + (lane & 7)) * 128);
    const uint32_t b_ch = (uint32_t)((lane >> 3) & 1);

    uint32_t Af[2][4][4], Bf[2][4][4];   // register double buffer

    auto load_frags = [&](uint32_t base, int ks, int buf) {
        const uint32_t ach = (((uint32_t)(ks * 2) + a_ch) ^ sel) << 4;
        const uint32_t bch = (((uint32_t)(ks * 2) + b_ch) ^ sel) << 4;
        #pragma unroll
        for (int mt = 0; mt < 4; ++mt)
            ldsm4(Af[buf][mt], base + a_rowoff + (uint32_t)(mt * 16 * 128) + ach);
        #pragma unroll
        for (int np = 0; np < 4; ++np)
            ldsm4(Bf[buf][np], base + 16384 + b_rowoff + (uint32_t)(np * 16 * 128) + bch);
    };

    auto mma_step = [&](int buf) {
        #pragma unroll
        for (int mt = 0; mt < 4; ++mt)
            #pragma unroll
            for (int np = 0; np < 4; ++np)
                #pragma unroll
                for (int h2 = 0; h2 < 2; ++h2)
                    mma_f16(acc[mt][np * 2 + h2], Af[buf][mt], &Bf[buf][np][h2 * 2]);
    };

    // ---- prologue ----
    load_stage(0, 0);
    asm volatile("cp.async.commit_group;" ::: "memory");
    load_stage(1, 1);
    asm volatile("cp.async.commit_group;" ::: "memory");
    asm volatile("cp.async.wait_group 1;" ::: "memory");  // G0 done -> stage 0 ready
    __syncthreads();
    load_frags(sb, 0, 0);                                 // chunk 0 ks0 -> buf0

    // ---- mainloop: barrier at tail; every chunk enters with ks0 in buf0 ----
    #pragma unroll 1
    for (int c = 0; c < NCHUNK; ++c) {
        if (c + 2 < NCHUNK) load_stage((c + 2) % 3, c + 2);
        asm volatile("cp.async.commit_group;" ::: "memory");  // empty commit near end keeps FIFO math valid
        const uint32_t base = sb + (uint32_t)((c % 3) * STAGE_B);
        load_frags(base, 1, 1); mma_step(0);
        load_frags(base, 2, 0); mma_step(1);
        load_frags(base, 3, 1); mma_step(0);
        // tail: ensure stage c+1 arrived (wait_group 1 -> G(c+1) retired) and visible
        asm volatile("cp.async.wait_group 1;" ::: "memory");
        __syncthreads();
        if (c + 1 < NCHUNK)
            load_frags(sb + (uint32_t)(((c + 1) % 3) * STAGE_B), 0, 0);  // next chunk ks0
        mma_step(1);                                       // hides the prefetch latency
    }

    // ---- epilogue ----
    const int gid = lane >> 2, tig = lane & 3;
    #pragma unroll
    for (int mt = 0; mt < 4; ++mt) {
        #pragma unroll
        for (int nt = 0; nt < 8; ++nt) {
            int row = m0 + warp_m * 64 + mt * 16 + gid;
            int col = n0 + warp_n * 64 + nt * 8 + tig * 2;
            float b0 = bias[col], b1 = bias[col + 1];
            float2 v0 = {acc[mt][nt][0] + b0, acc[mt][nt][1] + b1};
            float2 v1 = {acc[mt][nt][2] + b0, acc[mt][nt][3] + b1};
            *(float2*)(out + (size_t)row * NOUT + col) = v0;
            *(float2*)(out + (size_t)(row + 8) * NOUT + col) = v1;
        }
    }
}

// ===================== launcher =====================

extern "C" void kernel_launch(void* const* d_in, const int* in_sizes, int n_in,
                              void* d_out, int out_size) {
    const float* x = (const float*)d_in[0];
    const float* w = (const float*)d_in[1];
    const float* b = (const float*)d_in[2];
    float* out = (float*)d_out;

    cudaFuncSetAttribute(k_main, cudaFuncAttributeMaxDynamicSharedMemorySize, SMEM_BYTES);

    k_tab<<<(NFEAT + 255) / 256, 256>>>();
    k_wt<<<dim3(NFEAT / 64, NOUT / 64), 256>>>(w);
    k_expand<<<BATCH, 256>>>(x);
    k_main<<<dim3(NOUT / BN, BATCH / BM), THREADS, SMEM_BYTES>>>(b, out);
}